// round 2
// baseline (speedup 1.0000x reference)
#include <cuda_runtime.h>
#include <math.h>

#define BATCH 4
#define SEQ   4096
#define DIM   1024
#define NK    64
#define NTOK  (BATCH * SEQ)

typedef unsigned long long ull;

// Scratch (device globals — no allocation allowed)
__device__ float g_aff[NTOK * NK];          // 4 MB
__device__ float g_agg[BATCH * NK * DIM];   // 1 MB
__device__ float g_ss [BATCH * NK * DIM];   // 1 MB
__device__ float g_m2 [BATCH * NK * DIM];   // 1 MB
__device__ float g_c2 [NK];
__device__ float g_inv[NK];

__device__ __forceinline__ ull bcast2(float x) {
    ull r; asm("mov.b64 %0, {%1, %1};" : "=l"(r) : "f"(x)); return r;
}
__device__ __forceinline__ void ffma2(ull& d, ull a, ull b) {
    asm("fma.rn.f32x2 %0, %1, %2, %0;" : "+l"(d) : "l"(a), "l"(b));
}
union U64F2 { ull u; float2 f; };

// ---------------------------------------------------------------------------
// centers prep: c2[k] = |c_k|^2 ; inv[k] = -0.5 / clip(exp(ls),0.1,2)^2
// ---------------------------------------------------------------------------
__global__ void centers_prep(const float* __restrict__ centers,
                             const float* __restrict__ ls) {
    int c = blockIdx.x;
    int tid = threadIdx.x;
    float p = 0.f;
    for (int d = tid; d < DIM; d += 128) {
        float v = centers[c * DIM + d];
        p += v * v;
    }
    __shared__ float red[128];
    red[tid] = p;
    __syncthreads();
    for (int off = 64; off; off >>= 1) {
        if (tid < off) red[tid] += red[tid + off];
        __syncthreads();
    }
    if (tid == 0) {
        g_c2[c] = red[0];
        float s = expf(ls[c]);
        s = fminf(fmaxf(s, 0.1f), 2.0f);
        g_inv[c] = -0.5f / (s * s);
    }
}

// ---------------------------------------------------------------------------
// affinity: 128-token x 64-center tile per block, K-loop over DIM.
// xc GEMM with f32x2 micro-kernel (4 tok x 8 cent per thread), fused |x|^2,
// exp, row-normalize, coalesced writeout.
// ---------------------------------------------------------------------------
__global__ __launch_bounds__(256) void affinity_kernel(
        const float* __restrict__ x, const float* __restrict__ centers) {
    __shared__ float Xs[16][132];   // [k][token]
    __shared__ float Cs[16][68];    // [k][center]
    __shared__ float sOut[128][68]; // [token][center]
    __shared__ float x2s[128];
    __shared__ float sC2[NK], sInv[NK];

    int tid = threadIdx.x;
    int t0 = blockIdx.x * 128;
    if (tid < NK) { sC2[tid] = g_c2[tid]; sInv[tid] = g_inv[tid]; }
    if (tid < 128) x2s[tid] = 0.f;

    int ty = tid >> 3, cx = tid & 7;            // 32 tok-groups x 8 cent-groups
    int lr = tid >> 1, lc = (tid & 1) * 8;      // X tile load: 128 rows x 16 k
    int cr = tid >> 2, cc = (tid & 3) * 4;      // C tile load: 64 rows x 16 k

    ull acc[4][4];
#pragma unroll
    for (int i = 0; i < 4; i++)
#pragma unroll
        for (int j = 0; j < 4; j++) acc[i][j] = 0ull;

    __syncthreads();
    for (int kk = 0; kk < DIM; kk += 16) {
        float4 xv0 = *(const float4*)&x[(size_t)(t0 + lr) * DIM + kk + lc];
        float4 xv1 = *(const float4*)&x[(size_t)(t0 + lr) * DIM + kk + lc + 4];
        float4 cv  = *(const float4*)&centers[(size_t)cr * DIM + kk + cc];
        __syncthreads();
        Xs[lc + 0][lr] = xv0.x; Xs[lc + 1][lr] = xv0.y;
        Xs[lc + 2][lr] = xv0.z; Xs[lc + 3][lr] = xv0.w;
        Xs[lc + 4][lr] = xv1.x; Xs[lc + 5][lr] = xv1.y;
        Xs[lc + 6][lr] = xv1.z; Xs[lc + 7][lr] = xv1.w;
        Cs[cc + 0][cr] = cv.x;  Cs[cc + 1][cr] = cv.y;
        Cs[cc + 2][cr] = cv.z;  Cs[cc + 3][cr] = cv.w;
        float ssq = xv0.x * xv0.x + xv0.y * xv0.y + xv0.z * xv0.z + xv0.w * xv0.w
                  + xv1.x * xv1.x + xv1.y * xv1.y + xv1.z * xv1.z + xv1.w * xv1.w;
        atomicAdd(&x2s[lr], ssq);
        __syncthreads();
#pragma unroll
        for (int k = 0; k < 16; k++) {
            ull b0 = *(const ull*)&Cs[k][cx * 8 + 0];
            ull b1 = *(const ull*)&Cs[k][cx * 8 + 2];
            ull b2 = *(const ull*)&Cs[k][cx * 8 + 4];
            ull b3 = *(const ull*)&Cs[k][cx * 8 + 6];
#pragma unroll
            for (int i = 0; i < 4; i++) {
                ull a = bcast2(Xs[k][ty * 4 + i]);
                ffma2(acc[i][0], a, b0); ffma2(acc[i][1], a, b1);
                ffma2(acc[i][2], a, b2); ffma2(acc[i][3], a, b3);
            }
        }
    }
    __syncthreads();
#pragma unroll
    for (int i = 0; i < 4; i++)
#pragma unroll
        for (int j = 0; j < 4; j++) {
            U64F2 u; u.u = acc[i][j];
            *(float2*)&sOut[ty * 4 + i][cx * 8 + 2 * j] = u.f;
        }
    __syncthreads();

    if (tid < 128) {
        float x2 = x2s[tid];
        float sum = 0.f;
#pragma unroll 8
        for (int k = 0; k < NK; k++) {
            float d2 = fmaxf(x2 - 2.f * sOut[tid][k] + sC2[k], 0.f);
            float v = __expf(sInv[k] * d2);
            sOut[tid][k] = v;
            sum += v;
        }
        float inv = 1.f / (sum + 1e-8f);
#pragma unroll
        for (int k = 0; k < NK; k += 4) {
            float4 o = make_float4(sOut[tid][k] * inv, sOut[tid][k + 1] * inv,
                                   sOut[tid][k + 2] * inv, sOut[tid][k + 3] * inv);
            *(float4*)&g_aff[(size_t)(t0 + tid) * NK + k] = o;
        }
    }
}

// ---------------------------------------------------------------------------
// aggregate: agg[b,k,d] += sum_s aff[b,s,k] * x[b,s,d]
// 64k x 256d tile, 8x8 micro (f32x2), 256-s chunk per block, split-S atomics.
// ---------------------------------------------------------------------------
__global__ __launch_bounds__(256) void aggregate_kernel(const float* __restrict__ x) {
    int b  = blockIdx.z;
    int d0 = blockIdx.x * 256;
    int s0 = blockIdx.y * 256;
    __shared__ float As[16][68];    // [s][k]
    __shared__ float Bs[16][256];   // [s][d]

    int tid = threadIdx.x;
    int kg = tid >> 5, dg = tid & 31;       // 8 k-groups x 32 d-groups, 8x8 micro
    int ar = tid >> 4, ac = (tid & 15) * 4; // tile load indices

    ull acc[8][4];
#pragma unroll
    for (int i = 0; i < 8; i++)
#pragma unroll
        for (int j = 0; j < 4; j++) acc[i][j] = 0ull;

    for (int ss = 0; ss < 256; ss += 16) {
        size_t srow = (size_t)b * SEQ + s0 + ss + ar;
        float4 av = *(const float4*)&g_aff[srow * NK + ac];
        float4 bv[4];
#pragma unroll
        for (int q = 0; q < 4; q++)
            bv[q] = *(const float4*)&x[srow * DIM + d0 + ac + q * 64];
        __syncthreads();
        *(float4*)&As[ar][ac] = av;
#pragma unroll
        for (int q = 0; q < 4; q++)
            *(float4*)&Bs[ar][ac + q * 64] = bv[q];
        __syncthreads();
#pragma unroll
        for (int s2 = 0; s2 < 16; s2++) {
            ull bb[4];
#pragma unroll
            for (int j = 0; j < 4; j++)
                bb[j] = *(const ull*)&Bs[s2][dg * 8 + 2 * j];
#pragma unroll
            for (int i = 0; i < 8; i++) {
                ull a = bcast2(As[s2][kg * 8 + i]);
                ffma2(acc[i][0], a, bb[0]); ffma2(acc[i][1], a, bb[1]);
                ffma2(acc[i][2], a, bb[2]); ffma2(acc[i][3], a, bb[3]);
            }
        }
    }
#pragma unroll
    for (int i = 0; i < 8; i++)
#pragma unroll
        for (int j = 0; j < 4; j++) {
            U64F2 u; u.u = acc[i][j];
            float* dst = &g_agg[((size_t)(b * NK + kg * 8 + i)) * DIM + d0 + dg * 8 + 2 * j];
            atomicAdd(dst, u.f.x);
            atomicAdd(dst + 1, u.f.y);
        }
}

// ---------------------------------------------------------------------------
// gemm_nt: C[m,n] += sum_d A[m,d] * W[n,d]; M=256, N=DIM, split-K=8.
// 64m x 128n tile, 4x8 micro (f32x2). grid (4, 8, 8) = 256 blocks.
// ---------------------------------------------------------------------------
__global__ __launch_bounds__(256) void gemm_nt(const float* __restrict__ A,
                                               const float* __restrict__ W,
                                               float* __restrict__ C) {
    int m0 = blockIdx.x * 64, n0 = blockIdx.y * 128, d0 = blockIdx.z * 128;
    __shared__ float As[16][68];    // [d][m]
    __shared__ float Ws[16][132];   // [d][n]
    int tid = threadIdx.x;
    int ty = tid >> 4, tx = tid & 15;       // 16 m-groups x 16 n-groups
    int ar = tid >> 2, ac = (tid & 3) * 4;
    int wr = tid >> 1, wc = (tid & 1) * 8;

    ull acc[4][4];
#pragma unroll
    for (int i = 0; i < 4; i++)
#pragma unroll
        for (int j = 0; j < 4; j++) acc[i][j] = 0ull;

    for (int dd = d0; dd < d0 + 128; dd += 16) {
        float4 av  = *(const float4*)&A[(size_t)(m0 + ar) * DIM + dd + ac];
        float4 wv0 = *(const float4*)&W[(size_t)(n0 + wr) * DIM + dd + wc];
        float4 wv1 = *(const float4*)&W[(size_t)(n0 + wr) * DIM + dd + wc + 4];
        __syncthreads();
        As[ac + 0][ar] = av.x; As[ac + 1][ar] = av.y;
        As[ac + 2][ar] = av.z; As[ac + 3][ar] = av.w;
        Ws[wc + 0][wr] = wv0.x; Ws[wc + 1][wr] = wv0.y;
        Ws[wc + 2][wr] = wv0.z; Ws[wc + 3][wr] = wv0.w;
        Ws[wc + 4][wr] = wv1.x; Ws[wc + 5][wr] = wv1.y;
        Ws[wc + 6][wr] = wv1.z; Ws[wc + 7][wr] = wv1.w;
        __syncthreads();
#pragma unroll
        for (int k = 0; k < 16; k++) {
            ull b0 = *(const ull*)&Ws[k][tx * 8 + 0];
            ull b1 = *(const ull*)&Ws[k][tx * 8 + 2];
            ull b2 = *(const ull*)&Ws[k][tx * 8 + 4];
            ull b3 = *(const ull*)&Ws[k][tx * 8 + 6];
#pragma unroll
            for (int i = 0; i < 4; i++) {
                ull a = bcast2(As[k][ty * 4 + i]);
                ffma2(acc[i][0], a, b0); ffma2(acc[i][1], a, b1);
                ffma2(acc[i][2], a, b2); ffma2(acc[i][3], a, b3);
            }
        }
    }
#pragma unroll
    for (int i = 0; i < 4; i++)
#pragma unroll
        for (int j = 0; j < 4; j++) {
            U64F2 u; u.u = acc[i][j];
            float* dst = &C[(size_t)(m0 + ty * 4 + i) * DIM + n0 + tx * 8 + 2 * j];
            atomicAdd(dst, u.f.x);
            atomicAdd(dst + 1, u.f.y);
        }
}

// ---------------------------------------------------------------------------
// distribute: out[b,s,e] = sum_k aff[b,s,k] * m2[b,k,e]
// 128s x 128e tile, 8x8 micro (f32x2), k-loop 64 in 4 chunks. 1024 blocks.
// ---------------------------------------------------------------------------
__global__ __launch_bounds__(256) void distribute_kernel(float* __restrict__ out) {
    int b = blockIdx.z, e0 = blockIdx.x * 128, s0 = blockIdx.y * 128;
    __shared__ float sA[16][132];   // [k][s]
    __shared__ float sB[16][128];   // [k][e]
    int tid = threadIdx.x;
    int sg = tid >> 4, eg = tid & 15;       // 16 s-groups x 16 e-groups
    int ar = tid >> 1, ac = (tid & 1) * 8;
    int br = tid >> 4, bc = (tid & 15) * 4;

    ull acc[8][4];
#pragma unroll
    for (int i = 0; i < 8; i++)
#pragma unroll
        for (int j = 0; j < 4; j++) acc[i][j] = 0ull;

    for (int kk = 0; kk < NK; kk += 16) {
        float4 a0 = *(const float4*)&g_aff[(size_t)(b * SEQ + s0 + ar) * NK + kk + ac];
        float4 a1 = *(const float4*)&g_aff[(size_t)(b * SEQ + s0 + ar) * NK + kk + ac + 4];
        float4 b0 = *(const float4*)&g_m2[((size_t)b * NK + kk + br) * DIM + e0 + bc];
        float4 b1 = *(const float4*)&g_m2[((size_t)b * NK + kk + br) * DIM + e0 + bc + 64];
        __syncthreads();
        sA[ac + 0][ar] = a0.x; sA[ac + 1][ar] = a0.y;
        sA[ac + 2][ar] = a0.z; sA[ac + 3][ar] = a0.w;
        sA[ac + 4][ar] = a1.x; sA[ac + 5][ar] = a1.y;
        sA[ac + 6][ar] = a1.z; sA[ac + 7][ar] = a1.w;
        *(float4*)&sB[br][bc] = b0;
        *(float4*)&sB[br][bc + 64] = b1;
        __syncthreads();
#pragma unroll
        for (int k = 0; k < 16; k++) {
            ull bb[4];
#pragma unroll
            for (int j = 0; j < 4; j++)
                bb[j] = *(const ull*)&sB[k][eg * 8 + 2 * j];
#pragma unroll
            for (int i = 0; i < 8; i++) {
                ull a = bcast2(sA[k][sg * 8 + i]);
                ffma2(acc[i][0], a, bb[0]); ffma2(acc[i][1], a, bb[1]);
                ffma2(acc[i][2], a, bb[2]); ffma2(acc[i][3], a, bb[3]);
            }
        }
    }
#pragma unroll
    for (int i = 0; i < 8; i++) {
        U64F2 u0, u1, u2, u3;
        u0.u = acc[i][0]; u1.u = acc[i][1]; u2.u = acc[i][2]; u3.u = acc[i][3];
        size_t row = (size_t)(b * SEQ + s0 + sg * 8 + i) * DIM + e0 + eg * 8;
        *(float4*)&out[row]     = make_float4(u0.f.x, u0.f.y, u1.f.x, u1.f.y);
        *(float4*)&out[row + 4] = make_float4(u2.f.x, u2.f.y, u3.f.x, u3.f.y);
    }
}

// ---------------------------------------------------------------------------
extern "C" void kernel_launch(void* const* d_in, const int* in_sizes, int n_in,
                              void* d_out, int out_size) {
    const float* x       = (const float*)d_in[0];  // [4,4096,1024]
    const float* centers = (const float*)d_in[1];  // [64,1024]
    const float* ls      = (const float*)d_in[2];  // [64]
    const float* Wv      = (const float*)d_in[3];  // [1024,1024]
    const float* Wo      = (const float*)d_in[4];  // [1024,1024]
    float* out = (float*)d_out;

    void *p_agg, *p_ss, *p_m2;
    cudaGetSymbolAddress(&p_agg, g_agg);
    cudaGetSymbolAddress(&p_ss,  g_ss);
    cudaGetSymbolAddress(&p_m2,  g_m2);

    centers_prep<<<NK, 128>>>(centers, ls);
    cudaMemsetAsync(p_agg, 0, sizeof(float) * BATCH * NK * DIM);
    cudaMemsetAsync(p_ss,  0, sizeof(float) * BATCH * NK * DIM);
    cudaMemsetAsync(p_m2,  0, sizeof(float) * BATCH * NK * DIM);

    affinity_kernel<<<NTOK / 128, 256>>>(x, centers);
    aggregate_kernel<<<dim3(DIM / 256, SEQ / 256, BATCH), 256>>>(x);
    gemm_nt<<<dim3(4, 8, 8), 256>>>((const float*)p_agg, Wv, (float*)p_ss);
    gemm_nt<<<dim3(4, 8, 8), 256>>>((const float*)p_ss, Wo, (float*)p_m2);
    distribute_kernel<<<dim3(DIM / 128, SEQ / 128, BATCH), 256>>>(out);
}

// round 5
// speedup vs baseline: 1.5160x; 1.5160x over previous
#include <cuda_runtime.h>
#include <math.h>

#define BATCH 4
#define SEQ   4096
#define DIM   1024
#define NK    64
#define NTOK  (BATCH * SEQ)

typedef unsigned long long ull;
union U64F2 { ull u; float2 f; };

__device__ float g_aff[NTOK * NK];          // 4 MB
__device__ float g_agg[BATCH * NK * DIM];   // 1 MB
__device__ float g_ss [BATCH * NK * DIM];   // 1 MB
__device__ float g_m2 [BATCH * NK * DIM];   // 1 MB
__device__ float g_c2 [NK];
__device__ float g_inv[NK];

__device__ __forceinline__ ull bcast2(float x) {
    ull r; asm("mov.b64 %0, {%1, %1};" : "=l"(r) : "f"(x)); return r;
}
__device__ __forceinline__ void ffma2(ull& d, ull a, ull b) {
    asm("fma.rn.f32x2 %0, %1, %2, %0;" : "+l"(d) : "l"(a), "l"(b));
}
// vector global reduction: 4 floats (16B aligned) in one instruction
__device__ __forceinline__ void red4(float* p, ull u0, ull u1) {
    U64F2 a, b; a.u = u0; b.u = u1;
    asm volatile("red.global.add.v4.f32 [%0], {%1, %2, %3, %4};"
                 :: "l"(p), "f"(a.f.x), "f"(a.f.y), "f"(b.f.x), "f"(b.f.y)
                 : "memory");
}

// ---------------------------------------------------------------------------
__global__ void centers_prep(const float* __restrict__ centers,
                             const float* __restrict__ ls) {
    int c = blockIdx.x, tid = threadIdx.x;
    float p = 0.f;
    for (int d = tid; d < DIM; d += 128) {
        float v = centers[c * DIM + d];
        p += v * v;
    }
    __shared__ float red[128];
    red[tid] = p; __syncthreads();
    for (int off = 64; off; off >>= 1) {
        if (tid < off) red[tid] += red[tid + off];
        __syncthreads();
    }
    if (tid == 0) {
        g_c2[c] = red[0];
        float s = expf(ls[c]);
        s = fminf(fmaxf(s, 0.1f), 2.0f);
        g_inv[c] = -0.5f / (s * s);
    }
}

// ---------------------------------------------------------------------------
// affinity: 64tok x 64cent per block, grid 256. Double-buffered k-chunks of 16.
// micro 4x4 (f32x2); x^2 fused into load path; exp+normalize from registers.
// ---------------------------------------------------------------------------
__global__ __launch_bounds__(256) void affinity_kernel(
        const float* __restrict__ x, const float* __restrict__ centers) {
    __shared__ float Xs[2][16][68];
    __shared__ float Cs[2][16][68];
    __shared__ float x2s[64];
    __shared__ float sC2[NK], sInv[NK];

    int tid = threadIdx.x;
    int t0 = blockIdx.x * 64;
    if (tid < NK) { sC2[tid] = g_c2[tid]; sInv[tid] = g_inv[tid]; }

    int lr = tid >> 2, lc = (tid & 3) * 4;   // loader: row 0..63, k-col 0..12
    int tg = tid >> 4, cg = tid & 15;        // compute: toks tg*4.., cents cg*4..

    const float* xrow = x + (size_t)(t0 + lr) * DIM + lc;
    const float* crow = centers + (size_t)lr * DIM + lc;

    ull acc[4][2];
#pragma unroll
    for (int i = 0; i < 4; i++) { acc[i][0] = 0ull; acc[i][1] = 0ull; }
    float x2a = 0.f;

    float4 xv = *(const float4*)xrow;
    float4 cv = *(const float4*)crow;
    x2a += xv.x * xv.x + xv.y * xv.y + xv.z * xv.z + xv.w * xv.w;
    Xs[0][lc + 0][lr] = xv.x; Xs[0][lc + 1][lr] = xv.y;
    Xs[0][lc + 2][lr] = xv.z; Xs[0][lc + 3][lr] = xv.w;
    Cs[0][lc + 0][lr] = cv.x; Cs[0][lc + 1][lr] = cv.y;
    Cs[0][lc + 2][lr] = cv.z; Cs[0][lc + 3][lr] = cv.w;
    __syncthreads();

    for (int c = 0; c < 64; c++) {
        int cur = c & 1;
        if (c < 63) {
            xv = *(const float4*)(xrow + (c + 1) * 16);
            cv = *(const float4*)(crow + (c + 1) * 16);
        }
#pragma unroll
        for (int k = 0; k < 16; k++) {
            ulonglong2 b = *(const ulonglong2*)&Cs[cur][k][cg * 4];
            float4 av = *(const float4*)&Xs[cur][k][tg * 4];
            ull a0 = bcast2(av.x), a1 = bcast2(av.y),
                a2 = bcast2(av.z), a3 = bcast2(av.w);
            ffma2(acc[0][0], a0, b.x); ffma2(acc[0][1], a0, b.y);
            ffma2(acc[1][0], a1, b.x); ffma2(acc[1][1], a1, b.y);
            ffma2(acc[2][0], a2, b.x); ffma2(acc[2][1], a2, b.y);
            ffma2(acc[3][0], a3, b.x); ffma2(acc[3][1], a3, b.y);
        }
        __syncthreads();
        if (c < 63) {
            int nb = (c + 1) & 1;
            x2a += xv.x * xv.x + xv.y * xv.y + xv.z * xv.z + xv.w * xv.w;
            Xs[nb][lc + 0][lr] = xv.x; Xs[nb][lc + 1][lr] = xv.y;
            Xs[nb][lc + 2][lr] = xv.z; Xs[nb][lc + 3][lr] = xv.w;
            Cs[nb][lc + 0][lr] = cv.x; Cs[nb][lc + 1][lr] = cv.y;
            Cs[nb][lc + 2][lr] = cv.z; Cs[nb][lc + 3][lr] = cv.w;
            __syncthreads();
        }
    }
    // finalize per-token |x|^2 (4 consecutive lanes own one token row)
    x2a += __shfl_xor_sync(0xffffffffu, x2a, 1);
    x2a += __shfl_xor_sync(0xffffffffu, x2a, 2);
    if ((tid & 3) == 0) x2s[lr] = x2a;
    __syncthreads();

    // epilogue: exp + row-normalize from registers
    float c2c[4], invc[4];
#pragma unroll
    for (int j = 0; j < 4; j++) { c2c[j] = sC2[cg * 4 + j]; invc[j] = sInv[cg * 4 + j]; }
#pragma unroll
    for (int i = 0; i < 4; i++) {
        float x2 = x2s[tg * 4 + i];
        U64F2 u0, u1; u0.u = acc[i][0]; u1.u = acc[i][1];
        float v0 = __expf(invc[0] * fmaxf(x2 - 2.f * u0.f.x + c2c[0], 0.f));
        float v1 = __expf(invc[1] * fmaxf(x2 - 2.f * u0.f.y + c2c[1], 0.f));
        float v2 = __expf(invc[2] * fmaxf(x2 - 2.f * u1.f.x + c2c[2], 0.f));
        float v3 = __expf(invc[3] * fmaxf(x2 - 2.f * u1.f.y + c2c[3], 0.f));
        float rs = v0 + v1 + v2 + v3;
        rs += __shfl_xor_sync(0xffffffffu, rs, 1);
        rs += __shfl_xor_sync(0xffffffffu, rs, 2);
        rs += __shfl_xor_sync(0xffffffffu, rs, 4);
        rs += __shfl_xor_sync(0xffffffffu, rs, 8);
        float inv = 1.f / (rs + 1e-8f);
        float4 o = make_float4(v0 * inv, v1 * inv, v2 * inv, v3 * inv);
        *(float4*)&g_aff[(size_t)(t0 + tg * 4 + i) * NK + cg * 4] = o;
    }
}

// ---------------------------------------------------------------------------
// aggregate: agg[b,k,d] += sum_s aff[b,s,k]*x[b,s,d]; 64k x 256d tile,
// split-S=16 (256 s each, chunks of 16), micro 8x8, red.v4 epilogue.
// ---------------------------------------------------------------------------
__global__ __launch_bounds__(256) void aggregate_kernel(const float* __restrict__ x) {
    int b = blockIdx.z, d0 = blockIdx.x * 256, s0 = blockIdx.y * 256;
    __shared__ float As[2][16][68];
    __shared__ float Bs[2][16][256];
    int tid = threadIdx.x;
    int ar = tid >> 4, ac = (tid & 15) * 4;
    int kg = tid >> 5, dg = tid & 31;

    const float* affp = g_aff + (size_t)(b * SEQ + s0 + ar) * NK + ac;
    const float* xp   = x + (size_t)(b * SEQ + s0 + ar) * DIM + d0 + ac;

    ull acc[8][4];
#pragma unroll
    for (int i = 0; i < 8; i++)
#pragma unroll
        for (int j = 0; j < 4; j++) acc[i][j] = 0ull;

    float4 av = *(const float4*)affp;
    float4 b0v = *(const float4*)(xp);
    float4 b1v = *(const float4*)(xp + 64);
    float4 b2v = *(const float4*)(xp + 128);
    float4 b3v = *(const float4*)(xp + 192);
    *(float4*)&As[0][ar][ac] = av;
    *(float4*)&Bs[0][ar][ac] = b0v;       *(float4*)&Bs[0][ar][ac + 64] = b1v;
    *(float4*)&Bs[0][ar][ac + 128] = b2v; *(float4*)&Bs[0][ar][ac + 192] = b3v;
    __syncthreads();

    for (int c = 0; c < 16; c++) {
        int cur = c & 1;
        if (c < 15) {
            size_t so = (size_t)(c + 1) * 16;
            av = *(const float4*)(affp + so * NK);
            b0v = *(const float4*)(xp + so * DIM);
            b1v = *(const float4*)(xp + so * DIM + 64);
            b2v = *(const float4*)(xp + so * DIM + 128);
            b3v = *(const float4*)(xp + so * DIM + 192);
        }
#pragma unroll
        for (int s2 = 0; s2 < 16; s2++) {
            float4 a0 = *(const float4*)&As[cur][s2][kg * 8];
            float4 a1 = *(const float4*)&As[cur][s2][kg * 8 + 4];
            ulonglong2 bb0 = *(const ulonglong2*)&Bs[cur][s2][dg * 4];
            ulonglong2 bb1 = *(const ulonglong2*)&Bs[cur][s2][dg * 4 + 128];
            ull aa[8] = { bcast2(a0.x), bcast2(a0.y), bcast2(a0.z), bcast2(a0.w),
                          bcast2(a1.x), bcast2(a1.y), bcast2(a1.z), bcast2(a1.w) };
#pragma unroll
            for (int i = 0; i < 8; i++) {
                ffma2(acc[i][0], aa[i], bb0.x); ffma2(acc[i][1], aa[i], bb0.y);
                ffma2(acc[i][2], aa[i], bb1.x); ffma2(acc[i][3], aa[i], bb1.y);
            }
        }
        __syncthreads();
        if (c < 15) {
            int nb = (c + 1) & 1;
            *(float4*)&As[nb][ar][ac] = av;
            *(float4*)&Bs[nb][ar][ac] = b0v;       *(float4*)&Bs[nb][ar][ac + 64] = b1v;
            *(float4*)&Bs[nb][ar][ac + 128] = b2v; *(float4*)&Bs[nb][ar][ac + 192] = b3v;
            __syncthreads();
        }
    }
#pragma unroll
    for (int i = 0; i < 8; i++) {
        float* base = &g_agg[(size_t)(b * NK + kg * 8 + i) * DIM + d0];
        red4(base + dg * 4, acc[i][0], acc[i][1]);
        red4(base + dg * 4 + 128, acc[i][2], acc[i][3]);
    }
}

// ---------------------------------------------------------------------------
// gemm_nt: C[m,n] += sum_d A[m,d]*W[n,d]; M=256,N=1024, split-K=8.
// 64m x 128n tile, micro 4x8, double-buffered, red.v4 epilogue.
// ---------------------------------------------------------------------------
__global__ __launch_bounds__(256) void gemm_nt(const float* __restrict__ A,
                                               const float* __restrict__ W,
                                               float* __restrict__ C) {
    int m0 = blockIdx.x * 64, n0 = blockIdx.y * 128, d0 = blockIdx.z * 128;
    __shared__ float As[2][16][68];
    __shared__ float Ws[2][16][132];
    int tid = threadIdx.x;
    int lr = tid >> 2, lc = (tid & 3) * 4;   // A loader: 64 rows x 16 k
    int wr = tid >> 1, wc = (tid & 1) * 8;   // W loader: 128 rows x 16 k
    int tg = tid >> 4, ng = tid & 15;

    const float* ap = A + (size_t)(m0 + lr) * DIM + d0 + lc;
    const float* wp = W + (size_t)(n0 + wr) * DIM + d0 + wc;

    ull acc[4][4];
#pragma unroll
    for (int i = 0; i < 4; i++)
#pragma unroll
        for (int j = 0; j < 4; j++) acc[i][j] = 0ull;

    float4 av = *(const float4*)ap;
    float4 w0 = *(const float4*)wp;
    float4 w1 = *(const float4*)(wp + 4);
    As[0][lc + 0][lr] = av.x; As[0][lc + 1][lr] = av.y;
    As[0][lc + 2][lr] = av.z; As[0][lc + 3][lr] = av.w;
    Ws[0][wc + 0][wr] = w0.x; Ws[0][wc + 1][wr] = w0.y;
    Ws[0][wc + 2][wr] = w0.z; Ws[0][wc + 3][wr] = w0.w;
    Ws[0][wc + 4][wr] = w1.x; Ws[0][wc + 5][wr] = w1.y;
    Ws[0][wc + 6][wr] = w1.z; Ws[0][wc + 7][wr] = w1.w;
    __syncthreads();

    for (int c = 0; c < 8; c++) {
        int cur = c & 1;
        if (c < 7) {
            av = *(const float4*)(ap + (c + 1) * 16);
            w0 = *(const float4*)(wp + (c + 1) * 16);
            w1 = *(const float4*)(wp + (c + 1) * 16 + 4);
        }
#pragma unroll
        for (int k = 0; k < 16; k++) {
            float4 a = *(const float4*)&As[cur][k][tg * 4];
            ulonglong2 bb0 = *(const ulonglong2*)&Ws[cur][k][ng * 4];
            ulonglong2 bb1 = *(const ulonglong2*)&Ws[cur][k][ng * 4 + 64];
            ull a0 = bcast2(a.x), a1 = bcast2(a.y), a2 = bcast2(a.z), a3 = bcast2(a.w);
            ffma2(acc[0][0], a0, bb0.x); ffma2(acc[0][1], a0, bb0.y);
            ffma2(acc[0][2], a0, bb1.x); ffma2(acc[0][3], a0, bb1.y);
            ffma2(acc[1][0], a1, bb0.x); ffma2(acc[1][1], a1, bb0.y);
            ffma2(acc[1][2], a1, bb1.x); ffma2(acc[1][3], a1, bb1.y);
            ffma2(acc[2][0], a2, bb0.x); ffma2(acc[2][1], a2, bb0.y);
            ffma2(acc[2][2], a2, bb1.x); ffma2(acc[2][3], a2, bb1.y);
            ffma2(acc[3][0], a3, bb0.x); ffma2(acc[3][1], a3, bb0.y);
            ffma2(acc[3][2], a3, bb1.x); ffma2(acc[3][3], a3, bb1.y);
        }
        __syncthreads();
        if (c < 7) {
            int nb = (c + 1) & 1;
            As[nb][lc + 0][lr] = av.x; As[nb][lc + 1][lr] = av.y;
            As[nb][lc + 2][lr] = av.z; As[nb][lc + 3][lr] = av.w;
            Ws[nb][wc + 0][wr] = w0.x; Ws[nb][wc + 1][wr] = w0.y;
            Ws[nb][wc + 2][wr] = w0.z; Ws[nb][wc + 3][wr] = w0.w;
            Ws[nb][wc + 4][wr] = w1.x; Ws[nb][wc + 5][wr] = w1.y;
            Ws[nb][wc + 6][wr] = w1.z; Ws[nb][wc + 7][wr] = w1.w;
            __syncthreads();
        }
    }
#pragma unroll
    for (int i = 0; i < 4; i++) {
        float* base = &C[(size_t)(m0 + tg * 4 + i) * DIM + n0];
        red4(base + ng * 4, acc[i][0], acc[i][1]);
        red4(base + ng * 4 + 64, acc[i][2], acc[i][3]);
    }
}

// ---------------------------------------------------------------------------
// distribute: out[b,s,e] = sum_k aff[b,s,k]*m2[b,k,e]; 64s x 256e tile,
// micro 8x8, k in 4 chunks of 16, double-buffered, direct stores.
// ---------------------------------------------------------------------------
__global__ __launch_bounds__(256) void distribute_kernel(float* __restrict__ out) {
    int b = blockIdx.z, e0 = blockIdx.x * 256, s0 = blockIdx.y * 64;
    __shared__ float sA[2][16][68];
    __shared__ float sB[2][16][256];
    int tid = threadIdx.x;
    int lr = tid >> 2, lc = (tid & 3) * 4;   // aff loader (transpose): 64 s x 16 k
    int br = tid >> 4, bc = (tid & 15) * 4;  // m2 loader: 16 k x 256 e
    int sg = tid >> 5, eg = tid & 31;

    const float* affp = g_aff + (size_t)(b * SEQ + s0 + lr) * NK + lc;
    const float* mp   = g_m2 + (size_t)(b * NK + br) * DIM + e0 + bc;

    ull acc[8][4];
#pragma unroll
    for (int i = 0; i < 8; i++)
#pragma unroll
        for (int j = 0; j < 4; j++) acc[i][j] = 0ull;

    float4 av = *(const float4*)affp;
    float4 b0v = *(const float4*)(mp);
    float4 b1v = *(const float4*)(mp + 64);
    float4 b2v = *(const float4*)(mp + 128);
    float4 b3v = *(const float4*)(mp + 192);
    sA[0][lc + 0][lr] = av.x; sA[0][lc + 1][lr] = av.y;
    sA[0][lc + 2][lr] = av.z; sA[0][lc + 3][lr] = av.w;
    *(float4*)&sB[0][br][bc] = b0v;       *(float4*)&sB[0][br][bc + 64] = b1v;
    *(float4*)&sB[0][br][bc + 128] = b2v; *(float4*)&sB[0][br][bc + 192] = b3v;
    __syncthreads();

    for (int c = 0; c < 4; c++) {
        int cur = c & 1;
        if (c < 3) {
            av = *(const float4*)(affp + (c + 1) * 16);
            size_t ko = (size_t)(c + 1) * 16 * DIM;
            b0v = *(const float4*)(mp + ko);
            b1v = *(const float4*)(mp + ko + 64);
            b2v = *(const float4*)(mp + ko + 128);
            b3v = *(const float4*)(mp + ko + 192);
        }
#pragma unroll
        for (int k = 0; k < 16; k++) {
            float4 a0 = *(const float4*)&sA[cur][k][sg * 8];
            float4 a1 = *(const float4*)&sA[cur][k][sg * 8 + 4];
            ulonglong2 bb0 = *(const ulonglong2*)&sB[cur][k][eg * 4];
            ulonglong2 bb1 = *(const ulonglong2*)&sB[cur][k][eg * 4 + 128];
            ull aa[8] = { bcast2(a0.x), bcast2(a0.y), bcast2(a0.z), bcast2(a0.w),
                          bcast2(a1.x), bcast2(a1.y), bcast2(a1.z), bcast2(a1.w) };
#pragma unroll
            for (int i = 0; i < 8; i++) {
                ffma2(acc[i][0], aa[i], bb0.x); ffma2(acc[i][1], aa[i], bb0.y);
                ffma2(acc[i][2], aa[i], bb1.x); ffma2(acc[i][3], aa[i], bb1.y);
            }
        }
        __syncthreads();
        if (c < 3) {
            int nb = (c + 1) & 1;
            sA[nb][lc + 0][lr] = av.x; sA[nb][lc + 1][lr] = av.y;
            sA[nb][lc + 2][lr] = av.z; sA[nb][lc + 3][lr] = av.w;
            *(float4*)&sB[nb][br][bc] = b0v;       *(float4*)&sB[nb][br][bc + 64] = b1v;
            *(float4*)&sB[nb][br][bc + 128] = b2v; *(float4*)&sB[nb][br][bc + 192] = b3v;
            __syncthreads();
        }
    }
#pragma unroll
    for (int i = 0; i < 8; i++) {
        U64F2 u0, u1, u2, u3;
        u0.u = acc[i][0]; u1.u = acc[i][1]; u2.u = acc[i][2]; u3.u = acc[i][3];
        float* base = &out[(size_t)(b * SEQ + s0 + sg * 8 + i) * DIM + e0];
        *(float4*)(base + eg * 4) = make_float4(u0.f.x, u0.f.y, u1.f.x, u1.f.y);
        *(float4*)(base + eg * 4 + 128) = make_float4(u2.f.x, u2.f.y, u3.f.x, u3.f.y);
    }
}

// ---------------------------------------------------------------------------
extern "C" void kernel_launch(void* const* d_in, const int* in_sizes, int n_in,
                              void* d_out, int out_size) {
    const float* x       = (const float*)d_in[0];
    const float* centers = (const float*)d_in[1];
    const float* ls      = (const float*)d_in[2];
    const float* Wv      = (const float*)d_in[3];
    const float* Wo      = (const float*)d_in[4];
    float* out = (float*)d_out;

    void *p_agg, *p_ss, *p_m2;
    cudaGetSymbolAddress(&p_agg, g_agg);
    cudaGetSymbolAddress(&p_ss,  g_ss);
    cudaGetSymbolAddress(&p_m2,  g_m2);

    centers_prep<<<NK, 128>>>(centers, ls);
    cudaMemsetAsync(p_agg, 0, sizeof(float) * BATCH * NK * DIM);
    cudaMemsetAsync(p_ss,  0, sizeof(float) * BATCH * NK * DIM);
    cudaMemsetAsync(p_m2,  0, sizeof(float) * BATCH * NK * DIM);

    affinity_kernel<<<NTOK / 64, 256>>>(x, centers);
    aggregate_kernel<<<dim3(DIM / 256, SEQ / 256, BATCH), 256>>>(x);
    gemm_nt<<<dim3(4, 8, 8), 256>>>((const float*)p_agg, Wv, (float*)p_ss);
    gemm_nt<<<dim3(4, 8, 8), 256>>>((const float*)p_ss, Wo, (float*)p_m2);
    distribute_kernel<<<dim3(DIM / 256, SEQ / 64, BATCH), 256>>>(out);
}